// round 1
// baseline (speedup 1.0000x reference)
#include <cuda_runtime.h>
#include <cstdint>

// Problem constants
#define BQ   256
#define NM   500000
#define DIM  512
#define KSEL 5

// ---------------- scratch (no allocations allowed) ----------------
__device__ float g_d2[(size_t)BQ * NM];   // 512 MB
__device__ float g_msq[NM];
__device__ float g_qsq[BQ];

// ---------------- row squared-norms: one warp per row ----------------
__global__ void rowsq_kernel(const float* __restrict__ x, float* __restrict__ out, int rows) {
    int warp = (blockIdx.x * blockDim.x + threadIdx.x) >> 5;
    int lane = threadIdx.x & 31;
    if (warp >= rows) return;
    const float4* r = (const float4*)(x + (size_t)warp * DIM);
    float s = 0.f;
    #pragma unroll
    for (int i = lane; i < DIM / 4; i += 32) {
        float4 v = r[i];
        s += v.x * v.x + v.y * v.y + v.z * v.z + v.w * v.w;
    }
    #pragma unroll
    for (int o = 16; o; o >>= 1) s += __shfl_xor_sync(0xffffffff, s, o);
    if (lane == 0) out[warp] = s;
}

// ---------------- SGEMM-style d2 kernel ----------------
// Block tile: 128 (queries) x 128 (memory rows), K-tile 16, 256 threads, 8x8/thread.
#define BM 128
#define BN 128
#define BK 16
#define TM 8
#define TN 8
#define PAD 4

__global__ __launch_bounds__(256)
void gemm_d2_kernel(const float* __restrict__ Q, const float* __restrict__ M) {
    __shared__ float As[BK][BM + PAD];
    __shared__ float Bs[BK][BN + PAD];

    const int bn = blockIdx.x * BN;   // memory-row base
    const int bm = blockIdx.y * BM;   // query base
    const int tid = threadIdx.x;
    const int tx = tid % 16;          // memory-col group
    const int ty = tid / 16;          // query-row group

    const int lr = tid >> 2;          // 0..63 (load row)
    const int lc = (tid & 3) * 4;     // 0,4,8,12 (load col, float4)

    float acc[TM][TN];
    #pragma unroll
    for (int i = 0; i < TM; i++)
        #pragma unroll
        for (int j = 0; j < TN; j++) acc[i][j] = 0.f;

    for (int k0 = 0; k0 < DIM; k0 += BK) {
        // load A (query) tile, transposed into smem
        #pragma unroll
        for (int h = 0; h < 2; h++) {
            int row = lr + h * 64;
            float4 v = *(const float4*)(Q + (size_t)(bm + row) * DIM + k0 + lc);
            As[lc + 0][row] = v.x;
            As[lc + 1][row] = v.y;
            As[lc + 2][row] = v.z;
            As[lc + 3][row] = v.w;
        }
        // load B (memory) tile, transposed, guarded
        #pragma unroll
        for (int h = 0; h < 2; h++) {
            int row = lr + h * 64;
            int n = bn + row;
            float4 v = make_float4(0.f, 0.f, 0.f, 0.f);
            if (n < NM) v = *(const float4*)(M + (size_t)n * DIM + k0 + lc);
            Bs[lc + 0][row] = v.x;
            Bs[lc + 1][row] = v.y;
            Bs[lc + 2][row] = v.z;
            Bs[lc + 3][row] = v.w;
        }
        __syncthreads();

        #pragma unroll
        for (int kk = 0; kk < BK; kk++) {
            float af[TM], bf[TN];
            #pragma unroll
            for (int i = 0; i < TM; i++) af[i] = As[kk][ty * TM + i];
            #pragma unroll
            for (int j = 0; j < TN; j++) bf[j] = Bs[kk][tx * TN + j];
            #pragma unroll
            for (int i = 0; i < TM; i++)
                #pragma unroll
                for (int j = 0; j < TN; j++) acc[i][j] += af[i] * bf[j];
        }
        __syncthreads();
    }

    // epilogue: d2 = qsq + msq - 2*cross
    #pragma unroll
    for (int i = 0; i < TM; i++) {
        int q = bm + ty * TM + i;
        float qs = g_qsq[q];
        float* dst = g_d2 + (size_t)q * NM;
        #pragma unroll
        for (int j = 0; j < TN; j++) {
            int n = bn + tx * TN + j;
            if (n < NM) dst[n] = qs + g_msq[n] - 2.f * acc[i][j];
        }
    }
}

// ---------------- top-5 per query ----------------
#define TK_THREADS 1024
__global__ __launch_bounds__(TK_THREADS)
void topk_kernel(float* __restrict__ out) {
    const int q = blockIdx.x;
    const int tid = threadIdx.x;
    const float* row = g_d2 + (size_t)q * NM;

    float v[KSEL];
    int   id[KSEL];
    #pragma unroll
    for (int i = 0; i < KSEL; i++) { v[i] = 3.4e38f; id[i] = 0x7fffffff; }

    for (int n = tid; n < NM; n += TK_THREADS) {
        float d = row[n];
        if (d < v[KSEL - 1]) {
            // sorted insertion (ascending), strict < keeps earlier (smaller) index first on ties
            int pos = KSEL - 1;
            #pragma unroll
            for (int j = KSEL - 2; j >= 0; j--) {
                if (d < v[j]) { v[j + 1] = v[j]; id[j + 1] = id[j]; pos = j; }
            }
            v[pos] = d; id[pos] = n;
        }
    }

    __shared__ float sval[TK_THREADS];
    __shared__ int   sidx[TK_THREADS];
    int p = 0;  // how many of my candidates have been consumed

    for (int sel = 0; sel < KSEL; sel++) {
        sval[tid] = (p < KSEL) ? v[p] : 3.4e38f;
        sidx[tid] = (p < KSEL) ? id[p] : 0x7fffffff;
        __syncthreads();
        for (int s = TK_THREADS / 2; s > 0; s >>= 1) {
            if (tid < s) {
                float a = sval[tid], b = sval[tid + s];
                int   ai = sidx[tid], bi = sidx[tid + s];
                if (b < a || (b == a && bi < ai)) { sval[tid] = b; sidx[tid] = bi; }
            }
            __syncthreads();
        }
        float bestv = sval[0];
        int   besti = sidx[0];
        __syncthreads();
        if (p < KSEL && id[p] == besti) p++;   // unique global index -> exactly one thread advances
        if (tid == 0) {
            out[q * KSEL + sel] = bestv;                            // distances block
            out[BQ * KSEL + q * KSEL + sel] = (float)besti;         // indices block (as float)
        }
        __syncthreads();
    }
}

// ---------------- launcher ----------------
extern "C" void kernel_launch(void* const* d_in, const int* in_sizes, int n_in,
                              void* d_out, int out_size) {
    const float* query  = (const float*)d_in[0];
    const float* memory = (const float*)d_in[1];
    // Defensive: identify by size in case input order differs
    if (n_in >= 2 && in_sizes[0] != BQ * DIM && in_sizes[1] == BQ * DIM) {
        const float* t = query; query = memory; memory = t;
    }
    float* out = (float*)d_out;

    float* d_msq; cudaGetSymbolAddress((void**)&d_msq, g_msq);
    float* d_qsq; cudaGetSymbolAddress((void**)&d_qsq, g_qsq);

    // squared norms
    {
        int warps = NM;
        int blocks = (warps * 32 + 255) / 256;
        rowsq_kernel<<<blocks, 256>>>(memory, d_msq, NM);
        int qblocks = (BQ * 32 + 255) / 256;
        rowsq_kernel<<<qblocks, 256>>>(query, d_qsq, BQ);
    }

    // d2 GEMM
    {
        dim3 grid((NM + BN - 1) / BN, BQ / BM);
        gemm_d2_kernel<<<grid, 256>>>(query, memory);
    }

    // top-k
    topk_kernel<<<BQ, TK_THREADS>>>(out);
}

// round 3
// speedup vs baseline: 1.5355x; 1.5355x over previous
#include <cuda_runtime.h>
#include <cuda_bf16.h>
#include <cstdint>

// ---------------- problem constants ----------------
#define BQ    256
#define NM    500000
#define DIM   512
#define KSEL  5
#define KCAND 16

// ---------------- GEMM tiling ----------------
#define MT      128                 // memory rows per CTA
#define NQT     256                 // all queries
#define KC      64                  // K elems per stage chunk (128B rows)
#define GT      512                 // threads
#define NTILES  ((NM + MT - 1) / MT)        // 3907
#define NMP     (NTILES * MT)               // 500096
#define STAGE_B 49152               // A 16KB + B 32KB
#define SMEM_REQ (2 * STAGE_B + 1024)

// ---------------- device scratch (no allocs allowed) ----------------
__device__ float         g_d2[(size_t)BQ * NM];      // 512 MB
__device__ float         g_msq[NMP];                 // padded (zeros beyond NM)
__device__ float         g_qsq[BQ];
__device__ __nv_bfloat16 g_mh[(size_t)NMP * DIM];    // 512 MB
__device__ __nv_bfloat16 g_qh[BQ * DIM];

// ---------------- helpers ----------------
__device__ __forceinline__ uint32_t smem_u32(const void* p) {
    uint32_t a;
    asm("{ .reg .u64 t; cvta.to.shared.u64 t, %1; cvt.u32.u64 %0, t; }" : "=r"(a) : "l"(p));
    return a;
}
#define SWZ(o) ((o) ^ (((o) >> 3) & 0x70))

#define CP16(dst, src) \
    asm volatile("cp.async.cg.shared.global [%0], [%1], 16;" :: "r"(dst), "l"(src))

#define LDSM4(r, addr)                                                    \
    asm volatile("ldmatrix.sync.aligned.m8n8.x4.shared.b16 {%0,%1,%2,%3}, [%4];" \
                 : "=r"((r)[0]), "=r"((r)[1]), "=r"((r)[2]), "=r"((r)[3]) \
                 : "r"(addr))

#define MMA16816(d, a, b0, b1)                                            \
    asm volatile("mma.sync.aligned.m16n8k16.row.col.f32.bf16.bf16.f32 "   \
                 "{%0,%1,%2,%3}, {%4,%5,%6,%7}, {%8,%9}, {%0,%1,%2,%3};"  \
                 : "+f"((d)[0]), "+f"((d)[1]), "+f"((d)[2]), "+f"((d)[3]) \
                 : "r"((a)[0]), "r"((a)[1]), "r"((a)[2]), "r"((a)[3]),    \
                   "r"(b0), "r"(b1))

// ---------------- bf16 convert + squared-norm (one warp per row) ----------------
__global__ void split_kernel(const float* __restrict__ x,
                             __nv_bfloat16* __restrict__ hi,
                             float* __restrict__ sq, int rows) {
    int warp = (blockIdx.x * blockDim.x + threadIdx.x) >> 5;
    int lane = threadIdx.x & 31;
    if (warp >= rows) return;
    const float4* r = (const float4*)(x + (size_t)warp * DIM);
    __nv_bfloat162* h2 = (__nv_bfloat162*)(hi + (size_t)warp * DIM);
    float s = 0.f;
    #pragma unroll
    for (int i = lane; i < DIM / 4; i += 32) {
        float4 v = r[i];
        s += v.x * v.x + v.y * v.y + v.z * v.z + v.w * v.w;
        h2[2 * i]     = __floats2bfloat162_rn(v.x, v.y);
        h2[2 * i + 1] = __floats2bfloat162_rn(v.z, v.w);
    }
    #pragma unroll
    for (int o = 16; o; o >>= 1) s += __shfl_xor_sync(0xffffffff, s, o);
    if (lane == 0) sq[warp] = s;
}

// ---------------- bf16 HMMA GEMM -> d2 ----------------
// CTA: 128 rows x 256 queries. 16 warps: wm = wid>>3 (2 x 64 rows),
// wn = wid&7 (8 x 32 queries). Warp tile 64x32: 4 m16 x 4 n8 mma tiles.
__global__ __launch_bounds__(GT, 1)
void gemm_kernel() {
    extern __shared__ char dsm[];
    char* alig = (char*)(((uintptr_t)dsm + 1023) & ~(uintptr_t)1023);
    const uint32_t base = smem_u32(alig);

    const int tid  = threadIdx.x;
    const int wid  = tid >> 5;
    const int lane = tid & 31;
    const int wm   = wid >> 3;
    const int wn   = wid & 7;
    const size_t n0 = (size_t)blockIdx.x * MT;

    float acc[4][4][4];
    #pragma unroll
    for (int mt = 0; mt < 4; mt++)
        #pragma unroll
        for (int j = 0; j < 4; j++)
            #pragma unroll
            for (int e = 0; e < 4; e++) acc[mt][j][e] = 0.f;

    auto load_stage = [&](int kc, int s) {
        const uint32_t aB = base + s * STAGE_B;
        const uint32_t bB = aB + 16384;
        #pragma unroll
        for (int i = 0; i < 2; i++) {           // A: 128 rows x 8 chunks
            int c = tid + i * GT;
            int row = c >> 3, piece = c & 7;
            const char* src = (const char*)g_mh +
                (((n0 + (size_t)row) * DIM) + (size_t)kc * KC + piece * 8) * 2;
            CP16(aB + SWZ(row * 128 + piece * 16), src);
        }
        #pragma unroll
        for (int i = 0; i < 4; i++) {           // B: 256 rows x 8 chunks
            int c = tid + i * GT;
            int row = c >> 3, piece = c & 7;
            const char* src = (const char*)g_qh +
                (((size_t)row * DIM) + (size_t)kc * KC + piece * 8) * 2;
            CP16(bB + SWZ(row * 128 + piece * 16), src);
        }
        asm volatile("cp.async.commit_group;" ::: "memory");
    };

    load_stage(0, 0);
    load_stage(1, 1);

    #pragma unroll 1
    for (int kc = 0; kc < DIM / KC; kc++) {
        const int s = kc & 1;
        asm volatile("cp.async.wait_group 1;" ::: "memory");
        __syncthreads();

        const uint32_t aS = base + s * STAGE_B;
        const uint32_t bS = aS + 16384;
        #pragma unroll
        for (int kk = 0; kk < 4; kk++) {
            uint32_t af[4][4], bf[2][4];
            #pragma unroll
            for (int mt = 0; mt < 4; mt++) {
                int row = wm * 64 + mt * 16 + (lane & 15);
                LDSM4(af[mt], aS + SWZ(row * 128 + kk * 32 + (lane >> 4) * 16));
            }
            #pragma unroll
            for (int nt = 0; nt < 2; nt++) {
                int row = wn * 32 + nt * 16 + (lane & 15);
                LDSM4(bf[nt], bS + SWZ(row * 128 + kk * 32 + (lane >> 4) * 16));
            }
            #pragma unroll
            for (int mt = 0; mt < 4; mt++)
                #pragma unroll
                for (int j = 0; j < 4; j++)
                    MMA16816(acc[mt][j], af[mt], bf[j >> 1][j & 1], bf[j >> 1][(j & 1) + 2]);
        }
        __syncthreads();
        if (kc + 2 < DIM / KC) load_stage(kc + 2, s);
    }

    // ---- epilogue: smem transpose, add norms, coalesced float4 stores ----
    float* sd = (float*)alig;                   // 128 q x (128 rows + 4 pad)
    const int g  = lane >> 2;
    const int tg = lane & 3;
    #pragma unroll 1
    for (int h = 0; h < 2; h++) {
        if ((wn >> 2) == h) {
            #pragma unroll
            for (int mt = 0; mt < 4; mt++) {
                int rowb = wm * 64 + mt * 16 + g;
                #pragma unroll
                for (int j = 0; j < 4; j++) {
                    int qloc = wn * 32 + j * 8 + 2 * tg - h * 128;
                    sd[(qloc)     * 132 + rowb]     = acc[mt][j][0];
                    sd[(qloc + 1) * 132 + rowb]     = acc[mt][j][1];
                    sd[(qloc)     * 132 + rowb + 8] = acc[mt][j][2];
                    sd[(qloc + 1) * 132 + rowb + 8] = acc[mt][j][3];
                }
            }
        }
        __syncthreads();
        #pragma unroll
        for (int i = 0; i < 8; i++) {
            int idx = tid + i * GT;
            int q = idx >> 5, c4 = idx & 31;
            int qg = h * 128 + q;
            size_t nb = n0 + c4 * 4;
            float4 v  = *(float4*)&sd[q * 132 + c4 * 4];
            float4 ms = *(const float4*)&g_msq[nb];
            float qs  = g_qsq[qg];
            float4 o;
            o.x = qs + ms.x - 2.f * v.x;
            o.y = qs + ms.y - 2.f * v.y;
            o.z = qs + ms.z - 2.f * v.z;
            o.w = qs + ms.w - 2.f * v.w;
            if (nb + 3 < NM) {
                *(float4*)&g_d2[(size_t)qg * NM + nb] = o;
            } else {
                float ov[4] = {o.x, o.y, o.z, o.w};
                #pragma unroll
                for (int e = 0; e < 4; e++)
                    if (nb + e < NM) g_d2[(size_t)qg * NM + nb + e] = ov[e];
            }
        }
        __syncthreads();
    }
}

// ---------------- top-k: approx top-16 then exact fp32 rescoring ----------------
#define TK_THREADS 1024
__global__ __launch_bounds__(TK_THREADS)
void topk_kernel(const float* __restrict__ query, const float* __restrict__ memory,
                 float* __restrict__ out) {
    const int q = blockIdx.x;
    const int tid = threadIdx.x;
    const float4* row4 = (const float4*)(g_d2 + (size_t)q * NM);

    float v[KCAND];
    int   id[KCAND];
    #pragma unroll
    for (int i = 0; i < KCAND; i++) { v[i] = 3.4e38f; id[i] = 0x7fffffff; }

    for (int n4 = tid; n4 < NM / 4; n4 += TK_THREADS) {
        float4 d4 = row4[n4];
        float dv[4] = {d4.x, d4.y, d4.z, d4.w};
        #pragma unroll
        for (int e = 0; e < 4; e++) {
            float d = dv[e];
            if (d < v[KCAND - 1]) {
                int n = n4 * 4 + e;
                int pos = KCAND - 1;
                #pragma unroll
                for (int j = KCAND - 2; j >= 0; j--) {
                    if (d < v[j]) { v[j + 1] = v[j]; id[j + 1] = id[j]; pos = j; }
                }
                v[pos] = d; id[pos] = n;
            }
        }
    }

    __shared__ float sval[TK_THREADS];
    __shared__ int   sidx[TK_THREADS];
    __shared__ int   cid[KCAND];
    __shared__ float cex[KCAND];
    int p = 0;

    for (int sel = 0; sel < KCAND; sel++) {
        sval[tid] = (p < KCAND) ? v[p] : 3.4e38f;
        sidx[tid] = (p < KCAND) ? id[p] : 0x7fffffff;
        __syncthreads();
        for (int s = TK_THREADS / 2; s > 0; s >>= 1) {
            if (tid < s) {
                float a = sval[tid], b = sval[tid + s];
                int   ai = sidx[tid], bi = sidx[tid + s];
                if (b < a || (b == a && bi < ai)) { sval[tid] = b; sidx[tid] = bi; }
            }
            __syncthreads();
        }
        int besti = sidx[0];
        __syncthreads();
        if (p < KCAND && id[p] == besti) p++;
        if (tid == 0) cid[sel] = besti;
        __syncthreads();
    }

    // exact fp32 rescoring: one warp per candidate
    const int w = tid >> 5, lane = tid & 31;
    if (w < KCAND) {
        const int ci = cid[w];
        const float4* qr = (const float4*)(query + (size_t)q * DIM);
        const float4* mr = (const float4*)(memory + (size_t)ci * DIM);
        float s = 0.f;
        #pragma unroll
        for (int i = lane; i < DIM / 4; i += 32) {
            float4 a = qr[i], b = mr[i];
            s += a.x * b.x + a.y * b.y + a.z * b.z + a.w * b.w;
        }
        #pragma unroll
        for (int o = 16; o; o >>= 1) s += __shfl_xor_sync(0xffffffff, s, o);
        if (lane == 0) cex[w] = g_qsq[q] + g_msq[ci] - 2.f * s;
    }
    __syncthreads();

    if (tid == 0) {
        float e[KCAND]; int ii[KCAND];
        #pragma unroll
        for (int i = 0; i < KCAND; i++) { e[i] = cex[i]; ii[i] = cid[i]; }
        #pragma unroll
        for (int i = 1; i < KCAND; i++) {
            float ev = e[i]; int iv = ii[i];
            int j = i - 1;
            while (j >= 0 && (e[j] > ev || (e[j] == ev && ii[j] > iv))) {
                e[j + 1] = e[j]; ii[j + 1] = ii[j]; j--;
            }
            e[j + 1] = ev; ii[j + 1] = iv;
        }
        #pragma unroll
        for (int k = 0; k < KSEL; k++) {
            out[q * KSEL + k] = e[k];
            out[BQ * KSEL + q * KSEL + k] = (float)ii[k];
        }
    }
}

// ---------------- launcher ----------------
extern "C" void kernel_launch(void* const* d_in, const int* in_sizes, int n_in,
                              void* d_out, int out_size) {
    const float* query  = (const float*)d_in[0];
    const float* memory = (const float*)d_in[1];
    if (n_in >= 2 && in_sizes[0] != BQ * DIM && in_sizes[1] == BQ * DIM) {
        const float* t = query; query = memory; memory = t;
    }
    float* out = (float*)d_out;

    float* d_msq; cudaGetSymbolAddress((void**)&d_msq, g_msq);
    float* d_qsq; cudaGetSymbolAddress((void**)&d_qsq, g_qsq);
    __nv_bfloat16* d_mh; cudaGetSymbolAddress((void**)&d_mh, g_mh);
    __nv_bfloat16* d_qh; cudaGetSymbolAddress((void**)&d_qh, g_qh);

    split_kernel<<<(NM * 32 + 255) / 256, 256>>>(memory, d_mh, d_msq, NM);
    split_kernel<<<(BQ * 32 + 255) / 256, 256>>>(query, d_qh, d_qsq, BQ);

    cudaFuncSetAttribute(gemm_kernel, cudaFuncAttributeMaxDynamicSharedMemorySize,
                         SMEM_REQ);
    gemm_kernel<<<NTILES, GT, SMEM_REQ>>>();

    topk_kernel<<<BQ, TK_THREADS>>>(query, memory, out);
}

// round 6
// speedup vs baseline: 2.5610x; 1.6679x over previous
#include <cuda_runtime.h>
#include <cuda_bf16.h>
#include <cstdint>

// ---------------- problem constants ----------------
#define BQ    256
#define NM    500000
#define DIM   512
#define KSEL  5
#define KCAND 16

// ---------------- GEMM tiling ----------------
#define MT      128
#define KC      64
#define GT      512
#define NTILES  ((NM + MT - 1) / MT)        // 3907
#define NMP     (NTILES * MT)               // 500096
#define NSTAGE  3
#define STAGE_B 49152                        // A 16KB + B 32KB
#define SMEM_REQ (NSTAGE * STAGE_B + 1024)

// ---------------- candidate filtering ----------------
#define SEEDN   1024
#define CAP     16384
#define MARGIN  1.0f

// ---------------- device scratch ----------------
__device__ float         g_msq[NMP];
__device__ float         g_qsq[BQ];
__device__ __nv_bfloat16 g_mh[(size_t)NMP * DIM];
__device__ __nv_bfloat16 g_qh[BQ * DIM];
__device__ float         g_bound[BQ];
__device__ unsigned int  g_ccnt[BQ];
__device__ float         g_cd[(size_t)BQ * CAP];
__device__ int           g_ci[(size_t)BQ * CAP];

// ---------------- helpers ----------------
__device__ __forceinline__ uint32_t smem_u32(const void* p) {
    uint32_t a;
    asm("{ .reg .u64 t; cvta.to.shared.u64 t, %1; cvt.u32.u64 %0, t; }" : "=r"(a) : "l"(p));
    return a;
}
#define SWZ(o) ((o) ^ (((o) >> 3) & 0x70))
#define CP16(dst, src) \
    asm volatile("cp.async.cg.shared.global [%0], [%1], 16;" :: "r"(dst), "l"(src))
#define LDSM4(r, addr)                                                    \
    asm volatile("ldmatrix.sync.aligned.m8n8.x4.shared.b16 {%0,%1,%2,%3}, [%4];" \
                 : "=r"((r)[0]), "=r"((r)[1]), "=r"((r)[2]), "=r"((r)[3]) \
                 : "r"(addr))
#define MMA16816(d, a, b0, b1)                                            \
    asm volatile("mma.sync.aligned.m16n8k16.row.col.f32.bf16.bf16.f32 "   \
                 "{%0,%1,%2,%3}, {%4,%5,%6,%7}, {%8,%9}, {%0,%1,%2,%3};"  \
                 : "+f"((d)[0]), "+f"((d)[1]), "+f"((d)[2]), "+f"((d)[3]) \
                 : "r"((a)[0]), "r"((a)[1]), "r"((a)[2]), "r"((a)[3]),    \
                   "r"(b0), "r"(b1))

// ---------------- bf16 convert + squared-norm ----------------
__global__ void split_kernel(const float* __restrict__ x,
                             __nv_bfloat16* __restrict__ hi,
                             float* __restrict__ sq, int rows) {
    int warp = (blockIdx.x * blockDim.x + threadIdx.x) >> 5;
    int lane = threadIdx.x & 31;
    if (warp >= rows) return;
    const float4* r = (const float4*)(x + (size_t)warp * DIM);
    __nv_bfloat162* h2 = (__nv_bfloat162*)(hi + (size_t)warp * DIM);
    float s = 0.f;
    #pragma unroll
    for (int i = lane; i < DIM / 4; i += 32) {
        float4 v = r[i];
        s += v.x * v.x + v.y * v.y + v.z * v.z + v.w * v.w;
        h2[2 * i]     = __floats2bfloat162_rn(v.x, v.y);
        h2[2 * i + 1] = __floats2bfloat162_rn(v.z, v.w);
    }
    #pragma unroll
    for (int o = 16; o; o >>= 1) s += __shfl_xor_sync(0xffffffff, s, o);
    if (lane == 0) sq[warp] = s;
}

// ---------------- seed: bound[q] = approx 16th-smallest of first SEEDN rows ----------------
__global__ __launch_bounds__(256)
void seed_kernel(const float* __restrict__ query) {
    const int q = blockIdx.x;
    const int tid = threadIdx.x;
    __shared__ float qs[DIM];
    __shared__ float sd[SEEDN];
    __shared__ float rv[256];
    __shared__ int   ri[256];

    for (int i = tid; i < DIM; i += 256) qs[i] = query[(size_t)q * DIM + i];
    __syncthreads();

    const float qsq = g_qsq[q];
    for (int r = tid; r < SEEDN; r += 256) {
        const __nv_bfloat162* m2 = (const __nv_bfloat162*)(g_mh + (size_t)r * DIM);
        float dot = 0.f;
        #pragma unroll 8
        for (int i = 0; i < DIM / 2; i++) {
            float2 mv = __bfloat1622float2(m2[i]);
            dot += qs[2 * i] * mv.x + qs[2 * i + 1] * mv.y;
        }
        sd[r] = qsq + g_msq[r] - 2.f * dot;
    }
    __syncthreads();

    float last = 0.f;
    for (int sel = 0; sel < KCAND; sel++) {
        float bv = 3.4e38f; int bi = -1;
        #pragma unroll
        for (int k = 0; k < SEEDN / 256; k++) {
            int i = tid + k * 256;
            float v = sd[i];
            if (v < bv) { bv = v; bi = i; }
        }
        rv[tid] = bv; ri[tid] = bi;
        __syncthreads();
        for (int s = 128; s > 0; s >>= 1) {
            if (tid < s) {
                if (rv[tid + s] < rv[tid]) { rv[tid] = rv[tid + s]; ri[tid] = ri[tid + s]; }
            }
            __syncthreads();
        }
        if (tid == 0) { last = rv[0]; sd[ri[0]] = 3.4e38f; }
        __syncthreads();
    }
    if (tid == 0) g_bound[q] = last + MARGIN;
}

// ---------------- bf16 HMMA GEMM with fused candidate push ----------------
__global__ __launch_bounds__(GT, 1)
void gemm_kernel() {
    extern __shared__ char dsm[];
    __shared__ float s_qsq[BQ];
    __shared__ float s_bnd[BQ];
    char* alig = (char*)(((uintptr_t)dsm + 1023) & ~(uintptr_t)1023);
    const uint32_t base = smem_u32(alig);

    const int tid  = threadIdx.x;
    const int wid  = tid >> 5;
    const int lane = tid & 31;
    const int wm   = wid >> 3;
    const int wn   = wid & 7;
    const size_t n0 = (size_t)blockIdx.x * MT;

    if (tid < BQ) { s_qsq[tid] = g_qsq[tid]; s_bnd[tid] = g_bound[tid]; }
    if (tid + 256 < BQ) { /* BQ==256, unreachable */ }

    float acc[4][4][4];
    #pragma unroll
    for (int mt = 0; mt < 4; mt++)
        #pragma unroll
        for (int j = 0; j < 4; j++)
            #pragma unroll
            for (int e = 0; e < 4; e++) acc[mt][j][e] = 0.f;

    auto load_stage = [&](int kc, int s) {
        const uint32_t aB = base + s * STAGE_B;
        const uint32_t bB = aB + 16384;
        #pragma unroll
        for (int i = 0; i < 2; i++) {
            int c = tid + i * GT;
            int row = c >> 3, piece = c & 7;
            const char* src = (const char*)g_mh +
                (((n0 + (size_t)row) * DIM) + (size_t)kc * KC + piece * 8) * 2;
            CP16(aB + SWZ(row * 128 + piece * 16), src);
        }
        #pragma unroll
        for (int i = 0; i < 4; i++) {
            int c = tid + i * GT;
            int row = c >> 3, piece = c & 7;
            const char* src = (const char*)g_qh +
                (((size_t)row * DIM) + (size_t)kc * KC + piece * 8) * 2;
            CP16(bB + SWZ(row * 128 + piece * 16), src);
        }
        asm volatile("cp.async.commit_group;" ::: "memory");
    };

    load_stage(0, 0);
    load_stage(1, 1);
    load_stage(2, 2);

    #pragma unroll 1
    for (int kc = 0; kc < DIM / KC; kc++) {
        const int s = kc % NSTAGE;
        asm volatile("cp.async.wait_group %0;" :: "n"(NSTAGE - 1) : "memory");
        __syncthreads();

        const uint32_t aS = base + s * STAGE_B;
        const uint32_t bS = aS + 16384;
        #pragma unroll
        for (int kk = 0; kk < 4; kk++) {
            uint32_t af[4][4], bf[2][4];
            #pragma unroll
            for (int mt = 0; mt < 4; mt++) {
                int row = wm * 64 + mt * 16 + (lane & 15);
                LDSM4(af[mt], aS + SWZ(row * 128 + kk * 32 + (lane >> 4) * 16));
            }
            #pragma unroll
            for (int nt = 0; nt < 2; nt++) {
                int row = wn * 32 + nt * 16 + (lane & 15);
                LDSM4(bf[nt], bS + SWZ(row * 128 + kk * 32 + (lane >> 4) * 16));
            }
            #pragma unroll
            for (int mt = 0; mt < 4; mt++)
                #pragma unroll
                for (int j = 0; j < 4; j++)
                    MMA16816(acc[mt][j], af[mt], bf[j >> 1][j & 1], bf[j >> 1][(j & 1) + 2]);
        }
        __syncthreads();
        if (kc + NSTAGE < DIM / KC) load_stage(kc + NSTAGE, s);
    }

    // ---- fused epilogue: compare vs bound, push rare candidates ----
    const int g  = lane >> 2;
    const int tg = lane & 3;
    #pragma unroll
    for (int mt = 0; mt < 4; mt++) {
        const int r0 = wm * 64 + mt * 16 + g;
        const size_t gr0 = n0 + r0;
        const size_t gr1 = gr0 + 8;
        const float ms0 = g_msq[gr0];
        const float ms1 = g_msq[gr1];
        #pragma unroll
        for (int j = 0; j < 4; j++) {
            const int q0 = wn * 32 + j * 8 + 2 * tg;
            const int q1 = q0 + 1;
            const float qs0 = s_qsq[q0], qs1 = s_qsq[q1];
            const float b0 = s_bnd[q0],  b1 = s_bnd[q1];
            float d;
            d = qs0 + ms0 - 2.f * acc[mt][j][0];
            if (d < b0 && gr0 < NM) {
                unsigned pos = atomicAdd(&g_ccnt[q0], 1u);
                if (pos < CAP) { g_cd[(size_t)q0 * CAP + pos] = d; g_ci[(size_t)q0 * CAP + pos] = (int)gr0; }
            }
            d = qs1 + ms0 - 2.f * acc[mt][j][1];
            if (d < b1 && gr0 < NM) {
                unsigned pos = atomicAdd(&g_ccnt[q1], 1u);
                if (pos < CAP) { g_cd[(size_t)q1 * CAP + pos] = d; g_ci[(size_t)q1 * CAP + pos] = (int)gr0; }
            }
            d = qs0 + ms1 - 2.f * acc[mt][j][2];
            if (d < b0 && gr1 < NM) {
                unsigned pos = atomicAdd(&g_ccnt[q0], 1u);
                if (pos < CAP) { g_cd[(size_t)q0 * CAP + pos] = d; g_ci[(size_t)q0 * CAP + pos] = (int)gr1; }
            }
            d = qs1 + ms1 - 2.f * acc[mt][j][3];
            if (d < b1 && gr1 < NM) {
                unsigned pos = atomicAdd(&g_ccnt[q1], 1u);
                if (pos < CAP) { g_cd[(size_t)q1 * CAP + pos] = d; g_ci[(size_t)q1 * CAP + pos] = (int)gr1; }
            }
        }
    }
}

// ---------------- final: approx top-16 of candidates, exact rescoring, top-5 ----------------
#define FT 512
__global__ __launch_bounds__(FT)
void final_kernel(const float* __restrict__ query, const float* __restrict__ memory,
                  float* __restrict__ out) {
    const int q = blockIdx.x;
    const int tid = threadIdx.x;
    const int cnt = min((int)g_ccnt[q], CAP);
    const float* cd = g_cd + (size_t)q * CAP;
    const int*   ci = g_ci + (size_t)q * CAP;

    float v[KCAND];
    int   id[KCAND];
    #pragma unroll
    for (int i = 0; i < KCAND; i++) { v[i] = 3.4e38f; id[i] = 0x7fffffff; }

    for (int n = tid; n < cnt; n += FT) {
        float d = cd[n];
        int   ix = ci[n];
        if (d < v[KCAND - 1] || (d == v[KCAND - 1] && ix < id[KCAND - 1])) {
            int pos = KCAND - 1;
            #pragma unroll
            for (int j = KCAND - 2; j >= 0; j--) {
                if (d < v[j] || (d == v[j] && ix < id[j])) {
                    v[j + 1] = v[j]; id[j + 1] = id[j]; pos = j;
                }
            }
            v[pos] = d; id[pos] = ix;
        }
    }

    __shared__ float sval[FT];
    __shared__ int   sidx[FT];
    __shared__ int   cid[KCAND];
    __shared__ float cex[KCAND];
    int p = 0;

    for (int sel = 0; sel < KCAND; sel++) {
        sval[tid] = (p < KCAND) ? v[p] : 3.4e38f;
        sidx[tid] = (p < KCAND) ? id[p] : 0x7fffffff;
        __syncthreads();
        for (int s = FT / 2; s > 0; s >>= 1) {
            if (tid < s) {
                float a = sval[tid], b = sval[tid + s];
                int   ai = sidx[tid], bi = sidx[tid + s];
                if (b < a || (b == a && bi < ai)) { sval[tid] = b; sidx[tid] = bi; }
            }
            __syncthreads();
        }
        int besti = sidx[0];
        __syncthreads();
        if (p < KCAND && id[p] == besti) p++;
        if (tid == 0) cid[sel] = besti;
        __syncthreads();
    }

    // exact fp32 rescoring: one warp per candidate
    const int w = tid >> 5, lane = tid & 31;
    if (w < KCAND) {
        const int cix = cid[w];
        const float4* qr = (const float4*)(query + (size_t)q * DIM);
        const float4* mr = (const float4*)(memory + (size_t)cix * DIM);
        float s = 0.f;
        #pragma unroll
        for (int i = lane; i < DIM / 4; i += 32) {
            float4 a = qr[i], b = mr[i];
            s += a.x * b.x + a.y * b.y + a.z * b.z + a.w * b.w;
        }
        #pragma unroll
        for (int o = 16; o; o >>= 1) s += __shfl_xor_sync(0xffffffff, s, o);
        if (lane == 0) cex[w] = g_qsq[q] + g_msq[cix] - 2.f * s;
    }
    __syncthreads();

    if (tid == 0) {
        float e[KCAND]; int ii[KCAND];
        #pragma unroll
        for (int i = 0; i < KCAND; i++) { e[i] = cex[i]; ii[i] = cid[i]; }
        #pragma unroll
        for (int i = 1; i < KCAND; i++) {
            float ev = e[i]; int iv = ii[i];
            int j = i - 1;
            while (j >= 0 && (e[j] > ev || (e[j] == ev && ii[j] > iv))) {
                e[j + 1] = e[j]; ii[j + 1] = ii[j]; j--;
            }
            e[j + 1] = ev; ii[j + 1] = iv;
        }
        #pragma unroll
        for (int k = 0; k < KSEL; k++) {
            out[q * KSEL + k] = e[k];
            out[BQ * KSEL + q * KSEL + k] = (float)ii[k];
        }
    }
}

// ---------------- launcher ----------------
extern "C" void kernel_launch(void* const* d_in, const int* in_sizes, int n_in,
                              void* d_out, int out_size) {
    const float* query  = (const float*)d_in[0];
    const float* memory = (const float*)d_in[1];
    if (n_in >= 2 && in_sizes[0] != BQ * DIM && in_sizes[1] == BQ * DIM) {
        const float* t = query; query = memory; memory = t;
    }
    float* out = (float*)d_out;

    float* d_msq; cudaGetSymbolAddress((void**)&d_msq, g_msq);
    float* d_qsq; cudaGetSymbolAddress((void**)&d_qsq, g_qsq);
    __nv_bfloat16* d_mh; cudaGetSymbolAddress((void**)&d_mh, g_mh);
    __nv_bfloat16* d_qh; cudaGetSymbolAddress((void**)&d_qh, g_qh);
    unsigned int* d_ccnt; cudaGetSymbolAddress((void**)&d_ccnt, g_ccnt);

    cudaMemsetAsync(d_ccnt, 0, BQ * sizeof(unsigned int));

    split_kernel<<<(NM * 32 + 255) / 256, 256>>>(memory, d_mh, d_msq, NM);
    split_kernel<<<(BQ * 32 + 255) / 256, 256>>>(query, d_qh, d_qsq, BQ);

    seed_kernel<<<BQ, 256>>>(query);

    cudaFuncSetAttribute(gemm_kernel, cudaFuncAttributeMaxDynamicSharedMemorySize,
                         SMEM_REQ);
    gemm_kernel<<<NTILES, GT, SMEM_REQ>>>();

    final_kernel<<<BQ, FT>>>(query, memory, out);
}

// round 7
// speedup vs baseline: 2.8289x; 1.1046x over previous
#include <cuda_runtime.h>
#include <cuda_bf16.h>
#include <cstdint>

// ---------------- problem constants ----------------
#define BQ    256
#define NM    500000
#define DIM   512
#define KSEL  5
#define KCAND 16

// ---------------- GEMM tiling ----------------
#define MT      128                 // memory rows per CTA
#define NQT     128                 // queries per CTA (2 col tiles)
#define KC      64
#define GT      256                 // threads per CTA
#define NTILES  ((NM + MT - 1) / MT)        // 3907
#define NMP     (NTILES * MT)
#define NSTAGE  3
#define STAGE_B 32768                        // A 16KB + B 16KB
#define SMEM_REQ (NSTAGE * STAGE_B + 1024)

// ---------------- candidate filtering ----------------
#define SEEDN   1024
#define CAP     16384
#define MARGIN  1.0f

// ---------------- device scratch ----------------
__device__ float         g_msq[NMP];
__device__ float         g_qsq[BQ];
__device__ __nv_bfloat16 g_mh[(size_t)NMP * DIM];
__device__ __nv_bfloat16 g_qh[BQ * DIM];
__device__ float         g_bound[BQ];
__device__ unsigned int  g_ccnt[BQ];
__device__ float         g_cd[(size_t)BQ * CAP];
__device__ int           g_ci[(size_t)BQ * CAP];

// ---------------- helpers ----------------
__device__ __forceinline__ uint32_t smem_u32(const void* p) {
    uint32_t a;
    asm("{ .reg .u64 t; cvta.to.shared.u64 t, %1; cvt.u32.u64 %0, t; }" : "=r"(a) : "l"(p));
    return a;
}
#define SWZ(o) ((o) ^ (((o) >> 3) & 0x70))
#define CP16(dst, src) \
    asm volatile("cp.async.cg.shared.global [%0], [%1], 16;" :: "r"(dst), "l"(src))
#define LDSM4(r, addr)                                                    \
    asm volatile("ldmatrix.sync.aligned.m8n8.x4.shared.b16 {%0,%1,%2,%3}, [%4];" \
                 : "=r"((r)[0]), "=r"((r)[1]), "=r"((r)[2]), "=r"((r)[3]) \
                 : "r"(addr))
#define MMA16816(d, a, b0, b1)                                            \
    asm volatile("mma.sync.aligned.m16n8k16.row.col.f32.bf16.bf16.f32 "   \
                 "{%0,%1,%2,%3}, {%4,%5,%6,%7}, {%8,%9}, {%0,%1,%2,%3};"  \
                 : "+f"((d)[0]), "+f"((d)[1]), "+f"((d)[2]), "+f"((d)[3]) \
                 : "r"((a)[0]), "r"((a)[1]), "r"((a)[2]), "r"((a)[3]),    \
                   "r"(b0), "r"(b1))

// ---------------- bf16 convert + squared-norm ----------------
__global__ void split_kernel(const float* __restrict__ x,
                             __nv_bfloat16* __restrict__ hi,
                             float* __restrict__ sq, int rows) {
    int warp = (blockIdx.x * blockDim.x + threadIdx.x) >> 5;
    int lane = threadIdx.x & 31;
    if (warp >= rows) return;
    const float4* r = (const float4*)(x + (size_t)warp * DIM);
    __nv_bfloat162* h2 = (__nv_bfloat162*)(hi + (size_t)warp * DIM);
    float s = 0.f;
    #pragma unroll
    for (int i = lane; i < DIM / 4; i += 32) {
        float4 v = r[i];
        s += v.x * v.x + v.y * v.y + v.z * v.z + v.w * v.w;
        h2[2 * i]     = __floats2bfloat162_rn(v.x, v.y);
        h2[2 * i + 1] = __floats2bfloat162_rn(v.z, v.w);
    }
    #pragma unroll
    for (int o = 16; o; o >>= 1) s += __shfl_xor_sync(0xffffffff, s, o);
    if (lane == 0) sq[warp] = s;
}

// ---------------- seed: bound[q] = approx 16th-smallest of first SEEDN rows ----------------
__global__ __launch_bounds__(256)
void seed_kernel(const float* __restrict__ query) {
    const int q = blockIdx.x;
    const int tid = threadIdx.x;
    __shared__ float qs[DIM];
    __shared__ float sd[SEEDN];
    __shared__ float rv[256];
    __shared__ int   ri[256];

    for (int i = tid; i < DIM; i += 256) qs[i] = query[(size_t)q * DIM + i];
    __syncthreads();

    const float qsq = g_qsq[q];
    for (int r = tid; r < SEEDN; r += 256) {
        const __nv_bfloat162* m2 = (const __nv_bfloat162*)(g_mh + (size_t)r * DIM);
        float dot = 0.f;
        #pragma unroll 8
        for (int i = 0; i < DIM / 2; i++) {
            float2 mv = __bfloat1622float2(m2[i]);
            dot += qs[2 * i] * mv.x + qs[2 * i + 1] * mv.y;
        }
        sd[r] = qsq + g_msq[r] - 2.f * dot;
    }
    __syncthreads();

    float last = 0.f;
    for (int sel = 0; sel < KCAND; sel++) {
        float bv = 3.4e38f; int bi = -1;
        #pragma unroll
        for (int k = 0; k < SEEDN / 256; k++) {
            int i = tid + k * 256;
            float v = sd[i];
            if (v < bv) { bv = v; bi = i; }
        }
        rv[tid] = bv; ri[tid] = bi;
        __syncthreads();
        for (int s = 128; s > 0; s >>= 1) {
            if (tid < s) {
                if (rv[tid + s] < rv[tid]) { rv[tid] = rv[tid + s]; ri[tid] = ri[tid + s]; }
            }
            __syncthreads();
        }
        if (tid == 0) { last = rv[0]; sd[ri[0]] = 3.4e38f; }
        __syncthreads();
    }
    if (tid == 0) g_bound[q] = last + MARGIN;
}

// ---------------- bf16 HMMA GEMM with fused candidate push ----------------
// CTA: 128 rows x 128 queries, 256 threads, 8 warps (wm 2 x wn 4), warp 64x32.
__global__ __launch_bounds__(GT, 2)
void gemm_kernel() {
    extern __shared__ char dsm[];
    __shared__ float s_qsq[NQT];
    __shared__ float s_bnd[NQT];
    char* alig = (char*)(((uintptr_t)dsm + 1023) & ~(uintptr_t)1023);
    const uint32_t base = smem_u32(alig);

    const int tid  = threadIdx.x;
    const int wid  = tid >> 5;
    const int lane = tid & 31;
    const int wm   = wid >> 2;
    const int wn   = wid & 3;
    const size_t n0 = (size_t)blockIdx.x * MT;
    const int q0g   = blockIdx.y * NQT;

    if (tid < NQT) { s_qsq[tid] = g_qsq[q0g + tid]; s_bnd[tid] = g_bound[q0g + tid]; }

    float acc[4][4][4];
    #pragma unroll
    for (int mt = 0; mt < 4; mt++)
        #pragma unroll
        for (int j = 0; j < 4; j++)
            #pragma unroll
            for (int e = 0; e < 4; e++) acc[mt][j][e] = 0.f;

    auto load_stage = [&](int kc, int s) {
        const uint32_t aB = base + s * STAGE_B;
        const uint32_t bB = aB + 16384;
        #pragma unroll
        for (int i = 0; i < 4; i++) {           // A: 128 rows x 8 pieces
            int c = tid + i * GT;
            int row = c >> 3, piece = c & 7;
            const char* src = (const char*)g_mh +
                (((n0 + (size_t)row) * DIM) + (size_t)kc * KC + piece * 8) * 2;
            CP16(aB + SWZ(row * 128 + piece * 16), src);
        }
        #pragma unroll
        for (int i = 0; i < 4; i++) {           // B: 128 rows x 8 pieces
            int c = tid + i * GT;
            int row = c >> 3, piece = c & 7;
            const char* src = (const char*)g_qh +
                (((size_t)(q0g + row) * DIM) + (size_t)kc * KC + piece * 8) * 2;
            CP16(bB + SWZ(row * 128 + piece * 16), src);
        }
        asm volatile("cp.async.commit_group;" ::: "memory");
    };

    load_stage(0, 0);
    load_stage(1, 1);
    load_stage(2, 2);

    #pragma unroll 1
    for (int kc = 0; kc < DIM / KC; kc++) {
        const int s = kc % NSTAGE;
        asm volatile("cp.async.wait_group %0;" :: "n"(NSTAGE - 1) : "memory");
        __syncthreads();

        const uint32_t aS = base + s * STAGE_B;
        const uint32_t bS = aS + 16384;
        #pragma unroll
        for (int kk = 0; kk < 4; kk++) {
            uint32_t af[4][4], bf[2][4];
            #pragma unroll
            for (int mt = 0; mt < 4; mt++) {
                int row = wm * 64 + mt * 16 + (lane & 15);
                LDSM4(af[mt], aS + SWZ(row * 128 + kk * 32 + (lane >> 4) * 16));
            }
            #pragma unroll
            for (int nt = 0; nt < 2; nt++) {
                int row = wn * 32 + nt * 16 + (lane & 15);
                LDSM4(bf[nt], bS + SWZ(row * 128 + kk * 32 + (lane >> 4) * 16));
            }
            #pragma unroll
            for (int mt = 0; mt < 4; mt++)
                #pragma unroll
                for (int j = 0; j < 4; j++)
                    MMA16816(acc[mt][j], af[mt], bf[j >> 1][j & 1], bf[j >> 1][(j & 1) + 2]);
        }
        __syncthreads();
        if (kc + NSTAGE < DIM / KC) load_stage(kc + NSTAGE, s);
    }

    // ---- fused epilogue: compare vs bound, push rare candidates ----
    const int g  = lane >> 2;
    const int tg = lane & 3;
    #pragma unroll
    for (int mt = 0; mt < 4; mt++) {
        const int r0 = wm * 64 + mt * 16 + g;
        const size_t gr0 = n0 + r0;
        const size_t gr1 = gr0 + 8;
        const float ms0 = g_msq[gr0];
        const float ms1 = g_msq[gr1];
        #pragma unroll
        for (int j = 0; j < 4; j++) {
            const int ql0 = wn * 32 + j * 8 + 2 * tg;
            const int ql1 = ql0 + 1;
            const int q0 = q0g + ql0, q1 = q0g + ql1;
            const float qs0 = s_qsq[ql0], qs1 = s_qsq[ql1];
            const float b0 = s_bnd[ql0],  b1 = s_bnd[ql1];
            float d;
            d = qs0 + ms0 - 2.f * acc[mt][j][0];
            if (d < b0 && gr0 < NM) {
                unsigned pos = atomicAdd(&g_ccnt[q0], 1u);
                if (pos < CAP) { g_cd[(size_t)q0 * CAP + pos] = d; g_ci[(size_t)q0 * CAP + pos] = (int)gr0; }
            }
            d = qs1 + ms0 - 2.f * acc[mt][j][1];
            if (d < b1 && gr0 < NM) {
                unsigned pos = atomicAdd(&g_ccnt[q1], 1u);
                if (pos < CAP) { g_cd[(size_t)q1 * CAP + pos] = d; g_ci[(size_t)q1 * CAP + pos] = (int)gr0; }
            }
            d = qs0 + ms1 - 2.f * acc[mt][j][2];
            if (d < b0 && gr1 < NM) {
                unsigned pos = atomicAdd(&g_ccnt[q0], 1u);
                if (pos < CAP) { g_cd[(size_t)q0 * CAP + pos] = d; g_ci[(size_t)q0 * CAP + pos] = (int)gr1; }
            }
            d = qs1 + ms1 - 2.f * acc[mt][j][3];
            if (d < b1 && gr1 < NM) {
                unsigned pos = atomicAdd(&g_ccnt[q1], 1u);
                if (pos < CAP) { g_cd[(size_t)q1 * CAP + pos] = d; g_ci[(size_t)q1 * CAP + pos] = (int)gr1; }
            }
        }
    }
}

// ---------------- final: approx top-16 of candidates, exact rescoring, top-5 ----------------
#define FT 512
__global__ __launch_bounds__(FT)
void final_kernel(const float* __restrict__ query, const float* __restrict__ memory,
                  float* __restrict__ out) {
    const int q = blockIdx.x;
    const int tid = threadIdx.x;
    const int cnt = min((int)g_ccnt[q], CAP);
    const float* cd = g_cd + (size_t)q * CAP;
    const int*   ci = g_ci + (size_t)q * CAP;

    float v[KCAND];
    int   id[KCAND];
    #pragma unroll
    for (int i = 0; i < KCAND; i++) { v[i] = 3.4e38f; id[i] = 0x7fffffff; }

    for (int n = tid; n < cnt; n += FT) {
        float d = cd[n];
        int   ix = ci[n];
        if (d < v[KCAND - 1] || (d == v[KCAND - 1] && ix < id[KCAND - 1])) {
            int pos = KCAND - 1;
            #pragma unroll
            for (int j = KCAND - 2; j >= 0; j--) {
                if (d < v[j] || (d == v[j] && ix < id[j])) {
                    v[j + 1] = v[j]; id[j + 1] = id[j]; pos = j;
                }
            }
            v[pos] = d; id[pos] = ix;
        }
    }

    __shared__ float sval[FT];
    __shared__ int   sidx[FT];
    __shared__ int   cid[KCAND];
    __shared__ float cex[KCAND];
    int p = 0;

    for (int sel = 0; sel < KCAND; sel++) {
        sval[tid] = (p < KCAND) ? v[p] : 3.4e38f;
        sidx[tid] = (p < KCAND) ? id[p] : 0x7fffffff;
        __syncthreads();
        for (int s = FT / 2; s > 0; s >>= 1) {
            if (tid < s) {
                float a = sval[tid], b = sval[tid + s];
                int   ai = sidx[tid], bi = sidx[tid + s];
                if (b < a || (b == a && bi < ai)) { sval[tid] = b; sidx[tid] = bi; }
            }
            __syncthreads();
        }
        int besti = sidx[0];
        __syncthreads();
        if (p < KCAND && id[p] == besti) p++;
        if (tid == 0) cid[sel] = besti;
        __syncthreads();
    }

    const int w = tid >> 5, lane = tid & 31;
    if (w < KCAND) {
        const int cix = cid[w];
        const float4* qr = (const float4*)(query + (size_t)q * DIM);
        const float4* mr = (const float4*)(memory + (size_t)cix * DIM);
        float s = 0.f;
        #pragma unroll
        for (int i = lane; i < DIM / 4; i += 32) {
            float4 a = qr[i], b = mr[i];
            s += a.x * b.x + a.y * b.y + a.z * b.z + a.w * b.w;
        }
        #pragma unroll
        for (int o = 16; o; o >>= 1) s += __shfl_xor_sync(0xffffffff, s, o);
        if (lane == 0) cex[w] = g_qsq[q] + g_msq[cix] - 2.f * s;
    }
    __syncthreads();

    if (tid == 0) {
        float e[KCAND]; int ii[KCAND];
        #pragma unroll
        for (int i = 0; i < KCAND; i++) { e[i] = cex[i]; ii[i] = cid[i]; }
        #pragma unroll
        for (int i = 1; i < KCAND; i++) {
            float ev = e[i]; int iv = ii[i];
            int j = i - 1;
            while (j >= 0 && (e[j] > ev || (e[j] == ev && ii[j] > iv))) {
                e[j + 1] = e[j]; ii[j + 1] = ii[j]; j--;
            }
            e[j + 1] = ev; ii[j + 1] = iv;
        }
        #pragma unroll
        for (int k = 0; k < KSEL; k++) {
            out[q * KSEL + k] = e[k];
            out[BQ * KSEL + q * KSEL + k] = (float)ii[k];
        }
    }
}

// ---------------- launcher ----------------
extern "C" void kernel_launch(void* const* d_in, const int* in_sizes, int n_in,
                              void* d_out, int out_size) {
    const float* query  = (const float*)d_in[0];
    const float* memory = (const float*)d_in[1];
    if (n_in >= 2 && in_sizes[0] != BQ * DIM && in_sizes[1] == BQ * DIM) {
        const float* t = query; query = memory; memory = t;
    }
    float* out = (float*)d_out;

    float* d_msq; cudaGetSymbolAddress((void**)&d_msq, g_msq);
    float* d_qsq; cudaGetSymbolAddress((void**)&d_qsq, g_qsq);
    __nv_bfloat16* d_mh; cudaGetSymbolAddress((void**)&d_mh, g_mh);
    __nv_bfloat16* d_qh; cudaGetSymbolAddress((void**)&d_qh, g_qh);
    unsigned int* d_ccnt; cudaGetSymbolAddress((void**)&d_ccnt, g_ccnt);

    cudaMemsetAsync(d_ccnt, 0, BQ * sizeof(unsigned int));

    split_kernel<<<(NM * 32 + 255) / 256, 256>>>(memory, d_mh, d_msq, NM);
    split_kernel<<<(BQ * 32 + 255) / 256, 256>>>(query, d_qh, d_qsq, BQ);

    seed_kernel<<<BQ, 256>>>(query);

    cudaFuncSetAttribute(gemm_kernel, cudaFuncAttributeMaxDynamicSharedMemorySize,
                         SMEM_REQ);
    dim3 grid(NTILES, BQ / NQT);
    gemm_kernel<<<grid, GT, SMEM_REQ>>>();

    final_kernel<<<BQ, FT>>>(query, memory, out);
}

// round 8
// speedup vs baseline: 3.1920x; 1.1284x over previous
#include <cuda_runtime.h>
#include <cuda_bf16.h>
#include <cstdint>

// ---------------- problem constants ----------------
#define BQ    256
#define NM    500000
#define DIM   512
#define KSEL  5
#define KCAND 16

// ---------------- GEMM tiling ----------------
#define MT      128                 // memory rows per CTA
#define NQT     128                 // queries per CTA
#define KC      64
#define GT      256                 // threads per CTA
#define NCHUNK  (DIM / KC)          // 8
#define NTILES  ((NM + MT - 1) / MT)        // 3907
#define NMP     (NTILES * MT)
#define NSTAGE  3
#define STAGE_B 32768               // A 16KB + B 16KB
#define SMEM_REQ (NSTAGE * STAGE_B + 1024)

// ---------------- candidate filtering ----------------
#define SEEDN   1024
#define CAP     16384
#define MARGIN  1.0f

// ---------------- device scratch ----------------
__device__ float         g_msq[NMP];
__device__ float         g_qsq[BQ];
__device__ __nv_bfloat16 g_mh[(size_t)NMP * DIM];
__device__ __nv_bfloat16 g_qh[BQ * DIM];
__device__ float         g_bound[BQ];
__device__ unsigned int  g_ccnt[BQ];
__device__ float         g_cd[(size_t)BQ * CAP];
__device__ int           g_ci[(size_t)BQ * CAP];

// ---------------- helpers ----------------
__device__ __forceinline__ uint32_t smem_u32(const void* p) {
    uint32_t a;
    asm("{ .reg .u64 t; cvta.to.shared.u64 t, %1; cvt.u32.u64 %0, t; }" : "=r"(a) : "l"(p));
    return a;
}
#define SWZ(o) ((o) ^ (((o) >> 3) & 0x70))
#define CP16(dst, src) \
    asm volatile("cp.async.cg.shared.global [%0], [%1], 16;" :: "r"(dst), "l"(src))
#define LDSM4(r, addr)                                                    \
    asm volatile("ldmatrix.sync.aligned.m8n8.x4.shared.b16 {%0,%1,%2,%3}, [%4];" \
                 : "=r"((r)[0]), "=r"((r)[1]), "=r"((r)[2]), "=r"((r)[3]) \
                 : "r"(addr))
#define MMA16816(d, a, b0, b1)                                            \
    asm volatile("mma.sync.aligned.m16n8k16.row.col.f32.bf16.bf16.f32 "   \
                 "{%0,%1,%2,%3}, {%4,%5,%6,%7}, {%8,%9}, {%0,%1,%2,%3};"  \
                 : "+f"((d)[0]), "+f"((d)[1]), "+f"((d)[2]), "+f"((d)[3]) \
                 : "r"((a)[0]), "r"((a)[1]), "r"((a)[2]), "r"((a)[3]),    \
                   "r"(b0), "r"(b1))

// ---------------- bf16 convert + squared-norm ----------------
__global__ void split_kernel(const float* __restrict__ x,
                             __nv_bfloat16* __restrict__ hi,
                             float* __restrict__ sq, int rows) {
    int warp = (blockIdx.x * blockDim.x + threadIdx.x) >> 5;
    int lane = threadIdx.x & 31;
    if (warp >= rows) return;
    const float4* r = (const float4*)(x + (size_t)warp * DIM);
    __nv_bfloat162* h2 = (__nv_bfloat162*)(hi + (size_t)warp * DIM);
    float s = 0.f;
    #pragma unroll
    for (int i = lane; i < DIM / 4; i += 32) {
        float4 v = r[i];
        s += v.x * v.x + v.y * v.y + v.z * v.z + v.w * v.w;
        h2[2 * i]     = __floats2bfloat162_rn(v.x, v.y);
        h2[2 * i + 1] = __floats2bfloat162_rn(v.z, v.w);
    }
    #pragma unroll
    for (int o = 16; o; o >>= 1) s += __shfl_xor_sync(0xffffffff, s, o);
    if (lane == 0) sq[warp] = s;
}

// ---------------- seed: exact fp32, bound[q] = 16th-smallest of first SEEDN rows ----------------
__global__ __launch_bounds__(256)
void seed_kernel(const float* __restrict__ query, const float* __restrict__ memory) {
    const int q = blockIdx.x;
    const int tid = threadIdx.x;
    __shared__ float4 qs[DIM / 4];
    __shared__ float sd[SEEDN];
    __shared__ float rv[256];
    __shared__ int   ri[256];

    for (int i = tid; i < DIM / 4; i += 256)
        qs[i] = ((const float4*)(query + (size_t)q * DIM))[i];
    __syncthreads();

    for (int r = tid; r < SEEDN; r += 256) {
        const float4* m4 = (const float4*)(memory + (size_t)r * DIM);
        float d = 0.f;
        #pragma unroll 8
        for (int i = 0; i < DIM / 4; i++) {
            float4 a = qs[i], b = m4[i];
            float dx = a.x - b.x, dy = a.y - b.y, dz = a.z - b.z, dw = a.w - b.w;
            d += dx * dx + dy * dy + dz * dz + dw * dw;
        }
        sd[r] = d;
    }
    __syncthreads();

    float last = 0.f;
    for (int sel = 0; sel < KCAND; sel++) {
        float bv = 3.4e38f; int bi = -1;
        #pragma unroll
        for (int k = 0; k < SEEDN / 256; k++) {
            int i = tid + k * 256;
            float v = sd[i];
            if (v < bv) { bv = v; bi = i; }
        }
        rv[tid] = bv; ri[tid] = bi;
        __syncthreads();
        for (int s = 128; s > 0; s >>= 1) {
            if (tid < s) {
                if (rv[tid + s] < rv[tid]) { rv[tid] = rv[tid + s]; ri[tid] = ri[tid + s]; }
            }
            __syncthreads();
        }
        if (tid == 0) { last = rv[0]; sd[ri[0]] = 3.4e38f; }
        __syncthreads();
    }
    if (tid == 0) g_bound[q] = last + MARGIN;
}

// ---------------- bf16 HMMA GEMM with fused candidate push ----------------
// CTA: 128 rows x 128 queries, 256 threads, 8 warps (wm 2 x wn 4), warp 64x32.
// Single-sync 3-stage cp.async ring + double-buffered ldmatrix fragments.
__global__ __launch_bounds__(GT, 2)
void gemm_kernel() {
    extern __shared__ char dsm[];
    __shared__ float s_qsq[NQT];
    __shared__ float s_bnd[NQT];
    char* alig = (char*)(((uintptr_t)dsm + 1023) & ~(uintptr_t)1023);
    const uint32_t base = smem_u32(alig);

    const int tid  = threadIdx.x;
    const int wid  = tid >> 5;
    const int lane = tid & 31;
    const int wm   = wid >> 2;
    const int wn   = wid & 3;
    const size_t n0 = (size_t)blockIdx.x * MT;
    const int q0g   = blockIdx.y * NQT;

    if (tid < NQT) { s_qsq[tid] = g_qsq[q0g + tid]; s_bnd[tid] = g_bound[q0g + tid]; }

    float acc[4][4][4];
    #pragma unroll
    for (int mt = 0; mt < 4; mt++)
        #pragma unroll
        for (int j = 0; j < 4; j++)
            #pragma unroll
            for (int e = 0; e < 4; e++) acc[mt][j][e] = 0.f;

    auto load_stage = [&](int kc, int s) {
        const uint32_t aB = base + s * STAGE_B;
        const uint32_t bB = aB + 16384;
        #pragma unroll
        for (int i = 0; i < 4; i++) {           // A: 128 rows x 8 pieces
            int c = tid + i * GT;
            int row = c >> 3, piece = c & 7;
            const char* src = (const char*)g_mh +
                (((n0 + (size_t)row) * DIM) + (size_t)kc * KC + piece * 8) * 2;
            CP16(aB + SWZ(row * 128 + piece * 16), src);
        }
        #pragma unroll
        for (int i = 0; i < 4; i++) {           // B: 128 rows x 8 pieces
            int c = tid + i * GT;
            int row = c >> 3, piece = c & 7;
            const char* src = (const char*)g_qh +
                (((size_t)(q0g + row) * DIM) + (size_t)kc * KC + piece * 8) * 2;
            CP16(bB + SWZ(row * 128 + piece * 16), src);
        }
        asm volatile("cp.async.commit_group;" ::: "memory");
    };

    // prologue: prefetch depth 2
    load_stage(0, 0);
    load_stage(1, 1);

    const int arow = (lane & 15);
    const int ahalf = (lane >> 4) * 16;

    #pragma unroll 1
    for (int kc = 0; kc < NCHUNK; kc++) {
        const int s = kc % NSTAGE;
        if (kc + 2 < NCHUNK) {
            asm volatile("cp.async.wait_group 1;" ::: "memory");
        } else {
            asm volatile("cp.async.wait_group 0;" ::: "memory");
        }
        __syncthreads();
        // refill the stage consumed last iteration
        if (kc + 2 < NCHUNK) load_stage(kc + 2, (kc + 2) % NSTAGE);

        const uint32_t aS = base + s * STAGE_B;
        const uint32_t bS = aS + 16384;

        uint32_t af[2][4][4], bf[2][2][4];
        // prime kk = 0 fragments
        #pragma unroll
        for (int mt = 0; mt < 4; mt++) {
            int row = wm * 64 + mt * 16 + arow;
            LDSM4(af[0][mt], aS + SWZ(row * 128 + ahalf));
        }
        #pragma unroll
        for (int nt = 0; nt < 2; nt++) {
            int row = wn * 32 + nt * 16 + arow;
            LDSM4(bf[0][nt], bS + SWZ(row * 128 + ahalf));
        }

        #pragma unroll
        for (int kk = 0; kk < 4; kk++) {
            const int cur = kk & 1;
            const int nxt = cur ^ 1;
            if (kk < 3) {
                // prefetch kk+1 fragments ahead of this kk's MMA burst
                #pragma unroll
                for (int mt = 0; mt < 4; mt++) {
                    int row = wm * 64 + mt * 16 + arow;
                    LDSM4(af[nxt][mt], aS + SWZ(row * 128 + (kk + 1) * 32 + ahalf));
                }
                #pragma unroll
                for (int nt = 0; nt < 2; nt++) {
                    int row = wn * 32 + nt * 16 + arow;
                    LDSM4(bf[nxt][nt], bS + SWZ(row * 128 + (kk + 1) * 32 + ahalf));
                }
            }
            #pragma unroll
            for (int mt = 0; mt < 4; mt++)
                #pragma unroll
                for (int j = 0; j < 4; j++)
                    MMA16816(acc[mt][j], af[cur][mt],
                             bf[cur][j >> 1][j & 1], bf[cur][j >> 1][(j & 1) + 2]);
        }
    }

    // ---- fused epilogue: compare vs bound, push rare candidates ----
    const int g  = lane >> 2;
    const int tg = lane & 3;
    #pragma unroll
    for (int mt = 0; mt < 4; mt++) {
        const int r0 = wm * 64 + mt * 16 + g;
        const size_t gr0 = n0 + r0;
        const size_t gr1 = gr0 + 8;
        const float ms0 = g_msq[gr0];
        const float ms1 = g_msq[gr1];
        #pragma unroll
        for (int j = 0; j < 4; j++) {
            const int ql0 = wn * 32 + j * 8 + 2 * tg;
            const int ql1 = ql0 + 1;
            const int q0 = q0g + ql0, q1 = q0g + ql1;
            const float qs0 = s_qsq[ql0], qs1 = s_qsq[ql1];
            const float b0 = s_bnd[ql0],  b1 = s_bnd[ql1];
            float d;
            d = qs0 + ms0 - 2.f * acc[mt][j][0];
            if (d < b0 && gr0 < NM) {
                unsigned pos = atomicAdd(&g_ccnt[q0], 1u);
                if (pos < CAP) { g_cd[(size_t)q0 * CAP + pos] = d; g_ci[(size_t)q0 * CAP + pos] = (int)gr0; }
            }
            d = qs1 + ms0 - 2.f * acc[mt][j][1];
            if (d < b1 && gr0 < NM) {
                unsigned pos = atomicAdd(&g_ccnt[q1], 1u);
                if (pos < CAP) { g_cd[(size_t)q1 * CAP + pos] = d; g_ci[(size_t)q1 * CAP + pos] = (int)gr0; }
            }
            d = qs0 + ms1 - 2.f * acc[mt][j][2];
            if (d < b0 && gr1 < NM) {
                unsigned pos = atomicAdd(&g_ccnt[q0], 1u);
                if (pos < CAP) { g_cd[(size_t)q0 * CAP + pos] = d; g_ci[(size_t)q0 * CAP + pos] = (int)gr1; }
            }
            d = qs1 + ms1 - 2.f * acc[mt][j][3];
            if (d < b1 && gr1 < NM) {
                unsigned pos = atomicAdd(&g_ccnt[q1], 1u);
                if (pos < CAP) { g_cd[(size_t)q1 * CAP + pos] = d; g_ci[(size_t)q1 * CAP + pos] = (int)gr1; }
            }
        }
    }
}

// ---------------- final: approx top-16 of candidates, exact rescoring, top-5 ----------------
#define FT 512
__global__ __launch_bounds__(FT)
void final_kernel(const float* __restrict__ query, const float* __restrict__ memory,
                  float* __restrict__ out) {
    const int q = blockIdx.x;
    const int tid = threadIdx.x;
    const int cnt = min((int)g_ccnt[q], CAP);
    const float* cd = g_cd + (size_t)q * CAP;
    const int*   ci = g_ci + (size_t)q * CAP;

    float v[KCAND];
    int   id[KCAND];
    #pragma unroll
    for (int i = 0; i < KCAND; i++) { v[i] = 3.4e38f; id[i] = 0x7fffffff; }

    for (int n = tid; n < cnt; n += FT) {
        float d = cd[n];
        int   ix = ci[n];
        if (d < v[KCAND - 1] || (d == v[KCAND - 1] && ix < id[KCAND - 1])) {
            int pos = KCAND - 1;
            #pragma unroll
            for (int j = KCAND - 2; j >= 0; j--) {
                if (d < v[j] || (d == v[j] && ix < id[j])) {
                    v[j + 1] = v[j]; id[j + 1] = id[j]; pos = j;
                }
            }
            v[pos] = d; id[pos] = ix;
        }
    }

    __shared__ float sval[FT];
    __shared__ int   sidx[FT];
    __shared__ int   cid[KCAND];
    __shared__ float cex[KCAND];
    int p = 0;

    for (int sel = 0; sel < KCAND; sel++) {
        sval[tid] = (p < KCAND) ? v[p] : 3.4e38f;
        sidx[tid] = (p < KCAND) ? id[p] : 0x7fffffff;
        __syncthreads();
        for (int s = FT / 2; s > 0; s >>= 1) {
            if (tid < s) {
                float a = sval[tid], b = sval[tid + s];
                int   ai = sidx[tid], bi = sidx[tid + s];
                if (b < a || (b == a && bi < ai)) { sval[tid] = b; sidx[tid] = bi; }
            }
            __syncthreads();
        }
        int besti = sidx[0];
        __syncthreads();
        if (p < KCAND && id[p] == besti) p++;
        if (tid == 0) cid[sel] = besti;
        __syncthreads();
    }

    const int w = tid >> 5, lane = tid & 31;
    if (w < KCAND) {
        const int cix = cid[w];
        const float4* qr = (const float4*)(query + (size_t)q * DIM);
        const float4* mr = (const float4*)(memory + (size_t)cix * DIM);
        float s = 0.f;
        #pragma unroll
        for (int i = lane; i < DIM / 4; i += 32) {
            float4 a = qr[i], b = mr[i];
            s += a.x * b.x + a.y * b.y + a.z * b.z + a.w * b.w;
        }
        #pragma unroll
        for (int o = 16; o; o >>= 1) s += __shfl_xor_sync(0xffffffff, s, o);
        if (lane == 0) cex[w] = g_qsq[q] + g_msq[cix] - 2.f * s;
    }
    __syncthreads();

    if (tid == 0) {
        float e[KCAND]; int ii[KCAND];
        #pragma unroll
        for (int i = 0; i < KCAND; i++) { e[i] = cex[i]; ii[i] = cid[i]; }
        #pragma unroll
        for (int i = 1; i < KCAND; i++) {
            float ev = e[i]; int iv = ii[i];
            int j = i - 1;
            while (j >= 0 && (e[j] > ev || (e[j] == ev && ii[j] > iv))) {
                e[j + 1] = e[j]; ii[j + 1] = ii[j]; j--;
            }
            e[j + 1] = ev; ii[j + 1] = iv;
        }
        #pragma unroll
        for (int k = 0; k < KSEL; k++) {
            out[q * KSEL + k] = e[k];
            out[BQ * KSEL + q * KSEL + k] = (float)ii[k];
        }
    }
}

// ---------------- launcher ----------------
extern "C" void kernel_launch(void* const* d_in, const int* in_sizes, int n_in,
                              void* d_out, int out_size) {
    const float* query  = (const float*)d_in[0];
    const float* memory = (const float*)d_in[1];
    if (n_in >= 2 && in_sizes[0] != BQ * DIM && in_sizes[1] == BQ * DIM) {
        const float* t = query; query = memory; memory = t;
    }
    float* out = (float*)d_out;

    float* d_msq; cudaGetSymbolAddress((void**)&d_msq, g_msq);
    float* d_qsq; cudaGetSymbolAddress((void**)&d_qsq, g_qsq);
    __nv_bfloat16* d_mh; cudaGetSymbolAddress((void**)&d_mh, g_mh);
    __nv_bfloat16* d_qh; cudaGetSymbolAddress((void**)&d_qh, g_qh);
    unsigned int* d_ccnt; cudaGetSymbolAddress((void**)&d_ccnt, g_ccnt);

    cudaMemsetAsync(d_ccnt, 0, BQ * sizeof(unsigned int));

    seed_kernel<<<BQ, 256>>>(query, memory);

    split_kernel<<<(NM * 32 + 255) / 256, 256>>>(memory, d_mh, d_msq, NM);
    split_kernel<<<(BQ * 32 + 255) / 256, 256>>>(query, d_qh, d_qsq, BQ);

    cudaFuncSetAttribute(gemm_kernel, cudaFuncAttributeMaxDynamicSharedMemorySize,
                         SMEM_REQ);
    dim3 grid(NTILES, BQ / NQT);
    gemm_kernel<<<grid, GT, SMEM_REQ>>>();

    final_kernel<<<BQ, FT>>>(query, memory, out);
}

// round 9
// speedup vs baseline: 3.1981x; 1.0019x over previous
#include <cuda_runtime.h>
#include <cuda_bf16.h>
#include <cstdint>

// ---------------- problem constants ----------------
#define BQ    256
#define NM    500000
#define DIM   512
#define KSEL  5
#define KCAND 16

// ---------------- GEMM tiling ----------------
#define MT      128                 // memory rows per CTA
#define NQT     128                 // queries per CTA
#define KC      64
#define GT      256                 // threads per CTA
#define NCHUNK  (DIM / KC)          // 8
#define NTILES  ((NM + MT - 1) / MT)        // 3907
#define NMP     (NTILES * MT)
#define NSTAGE  3
#define STAGE_B 32768               // A 16KB + B 16KB
#define SMEM_REQ (NSTAGE * STAGE_B + 1024)

// ---------------- candidate filtering ----------------
#define SEEDN   1024
#define CAP     16384
#define MARGIN  1.0f

// ---------------- device scratch ----------------
__device__ float         g_msq[NMP];
__device__ float         g_qsq[BQ];
__device__ __nv_bfloat16 g_mh[(size_t)NMP * DIM];
__device__ __nv_bfloat16 g_qh[BQ * DIM];
__device__ float         g_bound[BQ];
__device__ unsigned int  g_ccnt[BQ];
__device__ float         g_cd[(size_t)BQ * CAP];
__device__ int           g_ci[(size_t)BQ * CAP];

// ---------------- helpers ----------------
__device__ __forceinline__ uint32_t smem_u32(const void* p) {
    uint32_t a;
    asm("{ .reg .u64 t; cvta.to.shared.u64 t, %1; cvt.u32.u64 %0, t; }" : "=r"(a) : "l"(p));
    return a;
}
#define SWZ(o) ((o) ^ (((o) >> 3) & 0x70))
#define CP16(dst, src) \
    asm volatile("cp.async.cg.shared.global [%0], [%1], 16;" :: "r"(dst), "l"(src))
#define LDSM4(r, addr)                                                    \
    asm volatile("ldmatrix.sync.aligned.m8n8.x4.shared.b16 {%0,%1,%2,%3}, [%4];" \
                 : "=r"((r)[0]), "=r"((r)[1]), "=r"((r)[2]), "=r"((r)[3]) \
                 : "r"(addr))
#define MMA16816(d, a, b0, b1)                                            \
    asm volatile("mma.sync.aligned.m16n8k16.row.col.f32.bf16.bf16.f32 "   \
                 "{%0,%1,%2,%3}, {%4,%5,%6,%7}, {%8,%9}, {%0,%1,%2,%3};"  \
                 : "+f"((d)[0]), "+f"((d)[1]), "+f"((d)[2]), "+f"((d)[3]) \
                 : "r"((a)[0]), "r"((a)[1]), "r"((a)[2]), "r"((a)[3]),    \
                   "r"(b0), "r"(b1))

// ---------------- bf16 convert + squared-norm ----------------
__global__ void split_kernel(const float* __restrict__ x,
                             __nv_bfloat16* __restrict__ hi,
                             float* __restrict__ sq, int rows) {
    int warp = (blockIdx.x * blockDim.x + threadIdx.x) >> 5;
    int lane = threadIdx.x & 31;
    if (warp >= rows) return;
    const float4* r = (const float4*)(x + (size_t)warp * DIM);
    __nv_bfloat162* h2 = (__nv_bfloat162*)(hi + (size_t)warp * DIM);
    float s = 0.f;
    #pragma unroll
    for (int i = lane; i < DIM / 4; i += 32) {
        float4 v = r[i];
        s += v.x * v.x + v.y * v.y + v.z * v.z + v.w * v.w;
        h2[2 * i]     = __floats2bfloat162_rn(v.x, v.y);
        h2[2 * i + 1] = __floats2bfloat162_rn(v.z, v.w);
    }
    #pragma unroll
    for (int o = 16; o; o >>= 1) s += __shfl_xor_sync(0xffffffff, s, o);
    if (lane == 0) sq[warp] = s;
}

// ---------------- seed: exact fp32, bound[q] = 16th-smallest of first SEEDN rows ----------------
__global__ __launch_bounds__(256)
void seed_kernel(const float* __restrict__ query, const float* __restrict__ memory) {
    const int q = blockIdx.x;
    const int tid = threadIdx.x;
    __shared__ float4 qs[DIM / 4];
    __shared__ float sd[SEEDN];
    __shared__ float rv[256];
    __shared__ int   ri[256];

    for (int i = tid; i < DIM / 4; i += 256)
        qs[i] = ((const float4*)(query + (size_t)q * DIM))[i];
    __syncthreads();

    for (int r = tid; r < SEEDN; r += 256) {
        const float4* m4 = (const float4*)(memory + (size_t)r * DIM);
        float d = 0.f;
        #pragma unroll 8
        for (int i = 0; i < DIM / 4; i++) {
            float4 a = qs[i], b = m4[i];
            float dx = a.x - b.x, dy = a.y - b.y, dz = a.z - b.z, dw = a.w - b.w;
            d += dx * dx + dy * dy + dz * dz + dw * dw;
        }
        sd[r] = d;
    }
    __syncthreads();

    float last = 0.f;
    for (int sel = 0; sel < KCAND; sel++) {
        float bv = 3.4e38f; int bi = -1;
        #pragma unroll
        for (int k = 0; k < SEEDN / 256; k++) {
            int i = tid + k * 256;
            float v = sd[i];
            if (v < bv) { bv = v; bi = i; }
        }
        rv[tid] = bv; ri[tid] = bi;
        __syncthreads();
        for (int s = 128; s > 0; s >>= 1) {
            if (tid < s) {
                if (rv[tid + s] < rv[tid]) { rv[tid] = rv[tid + s]; ri[tid] = ri[tid + s]; }
            }
            __syncthreads();
        }
        if (tid == 0) { last = rv[0]; sd[ri[0]] = 3.4e38f; }
        __syncthreads();
    }
    if (tid == 0) g_bound[q] = last + MARGIN;
}

// ---------------- bf16 HMMA GEMM with fused candidate push ----------------
// CTA: 128 rows x 128 queries, 256 threads, 8 warps (wm 2 x wn 4), warp 64x32.
// Single-sync 3-stage cp.async ring + double-buffered ldmatrix fragments.
__global__ __launch_bounds__(GT, 2)
void gemm_kernel() {
    extern __shared__ char dsm[];
    __shared__ float s_qsq[NQT];
    __shared__ float s_bnd[NQT];
    char* alig = (char*)(((uintptr_t)dsm + 1023) & ~(uintptr_t)1023);
    const uint32_t base = smem_u32(alig);

    const int tid  = threadIdx.x;
    const int wid  = tid >> 5;
    const int lane = tid & 31;
    const int wm   = wid >> 2;
    const int wn   = wid & 3;
    const size_t n0 = (size_t)blockIdx.x * MT;
    const int q0g   = blockIdx.y * NQT;

    if (tid < NQT) { s_qsq[tid] = g_qsq[q0g + tid]; s_bnd[tid] = g_bound[q0g + tid]; }

    float acc[4][4][4];
    #pragma unroll
    for (int mt = 0; mt < 4; mt++)
        #pragma unroll
        for (int j = 0; j < 4; j++)
            #pragma unroll
            for (int e = 0; e < 4; e++) acc[mt][j][e] = 0.f;

    auto load_stage = [&](int kc, int s) {
        const uint32_t aB = base + s * STAGE_B;
        const uint32_t bB = aB + 16384;
        #pragma unroll
        for (int i = 0; i < 4; i++) {           // A: 128 rows x 8 pieces
            int c = tid + i * GT;
            int row = c >> 3, piece = c & 7;
            const char* src = (const char*)g_mh +
                (((n0 + (size_t)row) * DIM) + (size_t)kc * KC + piece * 8) * 2;
            CP16(aB + SWZ(row * 128 + piece * 16), src);
        }
        #pragma unroll
        for (int i = 0; i < 4; i++) {           // B: 128 rows x 8 pieces
            int c = tid + i * GT;
            int row = c >> 3, piece = c & 7;
            const char* src = (const char*)g_qh +
                (((size_t)(q0g + row) * DIM) + (size_t)kc * KC + piece * 8) * 2;
            CP16(bB + SWZ(row * 128 + piece * 16), src);
        }
        asm volatile("cp.async.commit_group;" ::: "memory");
    };

    // prologue: prefetch depth 2
    load_stage(0, 0);
    load_stage(1, 1);

    const int arow = (lane & 15);
    const int ahalf = (lane >> 4) * 16;

    #pragma unroll 1
    for (int kc = 0; kc < NCHUNK; kc++) {
        const int s = kc % NSTAGE;
        if (kc + 2 < NCHUNK) {
            asm volatile("cp.async.wait_group 1;" ::: "memory");
        } else {
            asm volatile("cp.async.wait_group 0;" ::: "memory");
        }
        __syncthreads();
        // refill the stage consumed last iteration
        if (kc + 2 < NCHUNK) load_stage(kc + 2, (kc + 2) % NSTAGE);

        const uint32_t aS = base + s * STAGE_B;
        const uint32_t bS = aS + 16384;

        uint32_t af[2][4][4], bf[2][2][4];
        // prime kk = 0 fragments
        #pragma unroll
        for (int mt = 0; mt < 4; mt++) {
            int row = wm * 64 + mt * 16 + arow;
            LDSM4(af[0][mt], aS + SWZ(row * 128 + ahalf));
        }
        #pragma unroll
        for (int nt = 0; nt < 2; nt++) {
            int row = wn * 32 + nt * 16 + arow;
            LDSM4(bf[0][nt], bS + SWZ(row * 128 + ahalf));
        }

        #pragma unroll
        for (int kk = 0; kk < 4; kk++) {
            const int cur = kk & 1;
            const int nxt = cur ^ 1;
            if (kk < 3) {
                // prefetch kk+1 fragments ahead of this kk's MMA burst
                #pragma unroll
                for (int mt = 0; mt < 4; mt++) {
                    int row = wm * 64 + mt * 16 + arow;
                    LDSM4(af[nxt][mt], aS + SWZ(row * 128 + (kk + 1) * 32 + ahalf));
                }
                #pragma unroll
                for (int nt = 0; nt < 2; nt++) {
                    int row = wn * 32 + nt * 16 + arow;
                    LDSM4(bf[nxt][nt], bS + SWZ(row * 128 + (kk + 1) * 32 + ahalf));
                }
            }
            #pragma unroll
            for (int mt = 0; mt < 4; mt++)
                #pragma unroll
                for (int j = 0; j < 4; j++)
                    MMA16816(acc[mt][j], af[cur][mt],
                             bf[cur][j >> 1][j & 1], bf[cur][j >> 1][(j & 1) + 2]);
        }
    }

    // ---- fused epilogue: compare vs bound, push rare candidates ----
    const int g  = lane >> 2;
    const int tg = lane & 3;
    #pragma unroll
    for (int mt = 0; mt < 4; mt++) {
        const int r0 = wm * 64 + mt * 16 + g;
        const size_t gr0 = n0 + r0;
        const size_t gr1 = gr0 + 8;
        const float ms0 = g_msq[gr0];
        const float ms1 = g_msq[gr1];
        #pragma unroll
        for (int j = 0; j < 4; j++) {
            const int ql0 = wn * 32 + j * 8 + 2 * tg;
            const int ql1 = ql0 + 1;
            const int q0 = q0g + ql0, q1 = q0g + ql1;
            const float qs0 = s_qsq[ql0], qs1 = s_qsq[ql1];
            const float b0 = s_bnd[ql0],  b1 = s_bnd[ql1];
            float d;
            d = qs0 + ms0 - 2.f * acc[mt][j][0];
            if (d < b0 && gr0 < NM) {
                unsigned pos = atomicAdd(&g_ccnt[q0], 1u);
                if (pos < CAP) { g_cd[(size_t)q0 * CAP + pos] = d; g_ci[(size_t)q0 * CAP + pos] = (int)gr0; }
            }
            d = qs1 + ms0 - 2.f * acc[mt][j][1];
            if (d < b1 && gr0 < NM) {
                unsigned pos = atomicAdd(&g_ccnt[q1], 1u);
                if (pos < CAP) { g_cd[(size_t)q1 * CAP + pos] = d; g_ci[(size_t)q1 * CAP + pos] = (int)gr0; }
            }
            d = qs0 + ms1 - 2.f * acc[mt][j][2];
            if (d < b0 && gr1 < NM) {
                unsigned pos = atomicAdd(&g_ccnt[q0], 1u);
                if (pos < CAP) { g_cd[(size_t)q0 * CAP + pos] = d; g_ci[(size_t)q0 * CAP + pos] = (int)gr1; }
            }
            d = qs1 + ms1 - 2.f * acc[mt][j][3];
            if (d < b1 && gr1 < NM) {
                unsigned pos = atomicAdd(&g_ccnt[q1], 1u);
                if (pos < CAP) { g_cd[(size_t)q1 * CAP + pos] = d; g_ci[(size_t)q1 * CAP + pos] = (int)gr1; }
            }
        }
    }
}

// ---------------- final: approx top-16 of candidates, exact rescoring, top-5 ----------------
#define FT 512
__global__ __launch_bounds__(FT)
void final_kernel(const float* __restrict__ query, const float* __restrict__ memory,
                  float* __restrict__ out) {
    const int q = blockIdx.x;
    const int tid = threadIdx.x;
    const int cnt = min((int)g_ccnt[q], CAP);
    const float* cd = g_cd + (size_t)q * CAP;
    const int*   ci = g_ci + (size_t)q * CAP;

    float v[KCAND];
    int   id[KCAND];
    #pragma unroll
    for (int i = 0; i < KCAND; i++) { v[i] = 3.4e38f; id[i] = 0x7fffffff; }

    for (int n = tid; n < cnt; n += FT) {
        float d = cd[n];
        int   ix = ci[n];
        if (d < v[KCAND - 1] || (d == v[KCAND - 1] && ix < id[KCAND - 1])) {
            int pos = KCAND - 1;
            #pragma unroll
            for (int j = KCAND - 2; j >= 0; j--) {
                if (d < v[j] || (d == v[j] && ix < id[j])) {
                    v[j + 1] = v[j]; id[j + 1] = id[j]; pos = j;
                }
            }
            v[pos] = d; id[pos] = ix;
        }
    }

    __shared__ float sval[FT];
    __shared__ int   sidx[FT];
    __shared__ int   cid[KCAND];
    __shared__ float cex[KCAND];
    int p = 0;

    for (int sel = 0; sel < KCAND; sel++) {
        sval[tid] = (p < KCAND) ? v[p] : 3.4e38f;
        sidx[tid] = (p < KCAND) ? id[p] : 0x7fffffff;
        __syncthreads();
        for (int s = FT / 2; s > 0; s >>= 1) {
            if (tid < s) {
                float a = sval[tid], b = sval[tid + s];
                int   ai = sidx[tid], bi = sidx[tid + s];
                if (b < a || (b == a && bi < ai)) { sval[tid] = b; sidx[tid] = bi; }
            }
            __syncthreads();
        }
        int besti = sidx[0];
        __syncthreads();
        if (p < KCAND && id[p] == besti) p++;
        if (tid == 0) cid[sel] = besti;
        __syncthreads();
    }

    const int w = tid >> 5, lane = tid & 31;
    if (w < KCAND) {
        const int cix = cid[w];
        const float4* qr = (const float4*)(query + (size_t)q * DIM);
        const float4* mr = (const float4*)(memory + (size_t)cix * DIM);
        float s = 0.f;
        #pragma unroll
        for (int i = lane; i < DIM / 4; i += 32) {
            float4 a = qr[i], b = mr[i];
            s += a.x * b.x + a.y * b.y + a.z * b.z + a.w * b.w;
        }
        #pragma unroll
        for (int o = 16; o; o >>= 1) s += __shfl_xor_sync(0xffffffff, s, o);
        if (lane == 0) cex[w] = g_qsq[q] + g_msq[cix] - 2.f * s;
    }
    __syncthreads();

    if (tid == 0) {
        float e[KCAND]; int ii[KCAND];
        #pragma unroll
        for (int i = 0; i < KCAND; i++) { e[i] = cex[i]; ii[i] = cid[i]; }
        #pragma unroll
        for (int i = 1; i < KCAND; i++) {
            float ev = e[i]; int iv = ii[i];
            int j = i - 1;
            while (j >= 0 && (e[j] > ev || (e[j] == ev && ii[j] > iv))) {
                e[j + 1] = e[j]; ii[j + 1] = ii[j]; j--;
            }
            e[j + 1] = ev; ii[j + 1] = iv;
        }
        #pragma unroll
        for (int k = 0; k < KSEL; k++) {
            out[q * KSEL + k] = e[k];
            out[BQ * KSEL + q * KSEL + k] = (float)ii[k];
        }
    }
}

// ---------------- launcher ----------------
extern "C" void kernel_launch(void* const* d_in, const int* in_sizes, int n_in,
                              void* d_out, int out_size) {
    const float* query  = (const float*)d_in[0];
    const float* memory = (const float*)d_in[1];
    if (n_in >= 2 && in_sizes[0] != BQ * DIM && in_sizes[1] == BQ * DIM) {
        const float* t = query; query = memory; memory = t;
    }
    float* out = (float*)d_out;

    float* d_msq; cudaGetSymbolAddress((void**)&d_msq, g_msq);
    float* d_qsq; cudaGetSymbolAddress((void**)&d_qsq, g_qsq);
    __nv_bfloat16* d_mh; cudaGetSymbolAddress((void**)&d_mh, g_mh);
    __nv_bfloat16* d_qh; cudaGetSymbolAddress((void**)&d_qh, g_qh);
    unsigned int* d_ccnt; cudaGetSymbolAddress((void**)&d_ccnt, g_ccnt);

    cudaMemsetAsync(d_ccnt, 0, BQ * sizeof(unsigned int));

    seed_kernel<<<BQ, 256>>>(query, memory);

    split_kernel<<<(NM * 32 + 255) / 256, 256>>>(memory, d_mh, d_msq, NM);
    split_kernel<<<(BQ * 32 + 255) / 256, 256>>>(query, d_qh, d_qsq, BQ);

    cudaFuncSetAttribute(gemm_kernel, cudaFuncAttributeMaxDynamicSharedMemorySize,
                         SMEM_REQ);
    dim3 grid(NTILES, BQ / NQT);
    gemm_kernel<<<grid, GT, SMEM_REQ>>>();

    final_kernel<<<BQ, FT>>>(query, memory, out);
}